// round 2
// baseline (speedup 1.0000x reference)
#include <cuda_runtime.h>
#include <math.h>

// Problem constants
#define BB   2
#define SS   2048
#define DD   2048
#define HH   16
#define HD   128
#define DFF  8192
#define MROW (BB*SS)   // 4096
#define EPSV 1e-5f

// ---------------- scratch (device globals; allocation-free) ----------------
static __device__ float g_xn [(size_t)MROW*DD];
static __device__ float g_q  [(size_t)MROW*DD];
static __device__ float g_k  [(size_t)MROW*DD];
static __device__ float g_v  [(size_t)MROW*DD];
static __device__ float g_ctx[(size_t)MROW*DD];
static __device__ float g_h  [(size_t)MROW*DD];
static __device__ float g_ff [(size_t)MROW*DFF];

// ---------------- LayerNorm ----------------
__global__ __launch_bounds__(256)
void ln_kernel(const float* __restrict__ x, const float* __restrict__ sc,
               const float* __restrict__ sh, float* __restrict__ out) {
    int row = blockIdx.x;
    const float* xr = x + (size_t)row * DD;
    float v[8];
    float s = 0.f, sq = 0.f;
#pragma unroll
    for (int i = 0; i < 8; i++) {
        v[i] = xr[threadIdx.x + i*256];
        s  += v[i];
        sq += v[i]*v[i];
    }
    __shared__ float rs[8], rq[8];
    __shared__ float s_mean, s_rstd;
#pragma unroll
    for (int o = 16; o > 0; o >>= 1) {
        s  += __shfl_down_sync(0xFFFFFFFFu, s,  o);
        sq += __shfl_down_sync(0xFFFFFFFFu, sq, o);
    }
    int w = threadIdx.x >> 5;
    if ((threadIdx.x & 31) == 0) { rs[w] = s; rq[w] = sq; }
    __syncthreads();
    if (threadIdx.x == 0) {
        float ts = 0.f, tq = 0.f;
#pragma unroll
        for (int i = 0; i < 8; i++) { ts += rs[i]; tq += rq[i]; }
        float mean = ts * (1.0f/DD);
        float var  = tq * (1.0f/DD) - mean*mean;
        s_mean = mean;
        s_rstd = rsqrtf(var + EPSV);
    }
    __syncthreads();
    float mean = s_mean, rstd = s_rstd;
    float* orow = out + (size_t)row * DD;
#pragma unroll
    for (int i = 0; i < 8; i++) {
        int d = threadIdx.x + i*256;
        orow[d] = sc[d] * (v[i] - mean) * rstd + sh[d];
    }
}

// ---------------- GELU ----------------
__device__ __forceinline__ float gelu_f(float x) {
    float x3 = x*x*x;
    return 0.5f * x * (1.0f + tanhf(0.79788456080286536f * (x + 0.044715f*x3)));
}

// ---------------- GEMM: C[M,N] = A[M,K] @ B[K,N] (+epilogue) ----------------
// EPI 0: plain   EPI 1: +bias[n] + R[m,n]   EPI 2: gelu(+bias[n])
template<int EPI>
__global__ __launch_bounds__(256)
void gemm_kernel(const float* __restrict__ A, const float* __restrict__ Bm,
                 const float* __restrict__ bias, const float* __restrict__ R,
                 float* __restrict__ C, int N, int K) {
    __shared__ float As[16][132];
    __shared__ float Bs[16][128];
    int tid = threadIdx.x;
    int tx = tid & 15, ty = tid >> 4;
    int m0 = blockIdx.y * 128, n0 = blockIdx.x * 128;

    float acc[8][8];
#pragma unroll
    for (int i = 0; i < 8; i++)
#pragma unroll
        for (int j = 0; j < 8; j++) acc[i][j] = 0.f;

    int arow = tid >> 2;          // 0..63
    int akg  = (tid & 3) * 4;     // 0,4,8,12
    int brow = tid >> 5;          // 0..7
    int bcol = (tid & 31) * 4;    // 0..124

    const float* Aptr = A + (size_t)(m0 + arow) * K + akg;
    const float* Bptr = Bm + (size_t)brow * N + n0 + bcol;

    for (int kt = 0; kt < K; kt += 16) {
        float4 a0 = *(const float4*)(Aptr);
        float4 a1 = *(const float4*)(Aptr + (size_t)64 * K);
        float4 b0 = *(const float4*)(Bptr);
        float4 b1 = *(const float4*)(Bptr + (size_t)8 * N);
        As[akg+0][arow] = a0.x; As[akg+1][arow] = a0.y;
        As[akg+2][arow] = a0.z; As[akg+3][arow] = a0.w;
        As[akg+0][arow+64] = a1.x; As[akg+1][arow+64] = a1.y;
        As[akg+2][arow+64] = a1.z; As[akg+3][arow+64] = a1.w;
        *(float4*)&Bs[brow  ][bcol] = b0;
        *(float4*)&Bs[brow+8][bcol] = b1;
        __syncthreads();
#pragma unroll
        for (int k = 0; k < 16; k++) {
            float a[8], b[8];
            *(float4*)(a)   = *(float4*)&As[k][ty*8];
            *(float4*)(a+4) = *(float4*)&As[k][ty*8+4];
            *(float4*)(b)   = *(float4*)&Bs[k][tx*8];
            *(float4*)(b+4) = *(float4*)&Bs[k][tx*8+4];
#pragma unroll
            for (int i = 0; i < 8; i++)
#pragma unroll
                for (int j = 0; j < 8; j++)
                    acc[i][j] += a[i]*b[j];
        }
        __syncthreads();
        Aptr += 16;
        Bptr += (size_t)16 * N;
    }

#pragma unroll
    for (int i = 0; i < 8; i++) {
        int m = m0 + ty*8 + i;
#pragma unroll
        for (int j = 0; j < 8; j += 4) {
            int n = n0 + tx*8 + j;
            float4 o;
            float vv[4];
#pragma unroll
            for (int u = 0; u < 4; u++) vv[u] = acc[i][j+u];
            if (EPI == 1) {
                float4 bb = *(const float4*)(bias + n);
                float4 rr = *(const float4*)(R + (size_t)m * N + n);
                vv[0] += bb.x + rr.x; vv[1] += bb.y + rr.y;
                vv[2] += bb.z + rr.z; vv[3] += bb.w + rr.w;
            } else if (EPI == 2) {
                float4 bb = *(const float4*)(bias + n);
                vv[0] = gelu_f(vv[0] + bb.x); vv[1] = gelu_f(vv[1] + bb.y);
                vv[2] = gelu_f(vv[2] + bb.z); vv[3] = gelu_f(vv[3] + bb.w);
            }
            o.x = vv[0]; o.y = vv[1]; o.z = vv[2]; o.w = vv[3];
            *(float4*)(C + (size_t)m * N + n) = o;
        }
    }
}

// ---------------- Causal flash attention ----------------
// Q/K/V layout: [B,S,D] with head h occupying cols h*HD..h*HD+127.
// Block: 256 threads, 64 queries x (tiles of 64 keys). Dynamic smem.
#define ATT_SMEM_FLOATS (128*68 + 128*68 + 64*128 + 64*68 + 3*64)
#define ATT_SMEM_BYTES  (ATT_SMEM_FLOATS * 4)

__global__ __launch_bounds__(256)
void attn_kernel(const float* __restrict__ Q, const float* __restrict__ Kg,
                 const float* __restrict__ V, float* __restrict__ O) {
    extern __shared__ float sm[];
    float* Qt   = sm;                  // [128][68] transposed, pre-scaled
    float* Kt   = Qt + 128*68;         // [128][68] transposed
    float* Vs   = Kt + 128*68;         // [64][128]
    float* Ps   = Vs + 64*128;         // [64][68]
    float* mrow = Ps + 64*68;          // [64]
    float* lrow = mrow + 64;           // [64]
    float* frow = lrow + 64;           // [64]

    int tid = threadIdx.x;
    int tx = tid & 15, ty = tid >> 4;
    int q0 = blockIdx.x * 64;
    int b  = blockIdx.y >> 4;
    int h  = blockIdx.y & 15;
    const float rscale = 0.08838834764831845f;  // 1/sqrt(128)

    size_t base = ((size_t)b * SS) * DD + (size_t)h * HD;

    // load Q tile transposed + pre-scaled
#pragma unroll
    for (int i = 0; i < 8; i++) {
        int lin = tid + i*256;
        int r = lin >> 5;
        int d = (lin & 31) * 4;
        float4 qv = *(const float4*)(Q + base + (size_t)(q0 + r) * DD + d);
        Qt[(d+0)*68 + r] = qv.x * rscale;
        Qt[(d+1)*68 + r] = qv.y * rscale;
        Qt[(d+2)*68 + r] = qv.z * rscale;
        Qt[(d+3)*68 + r] = qv.w * rscale;
    }
    if (tid < 64) { mrow[tid] = -1e30f; lrow[tid] = 0.f; }

    float acc[4][8];
#pragma unroll
    for (int i = 0; i < 4; i++)
#pragma unroll
        for (int j = 0; j < 8; j++) acc[i][j] = 0.f;

    int ntiles = (q0 >> 6) + 1;
    for (int kt = 0; kt < ntiles; kt++) {
        int k0 = kt * 64;
        __syncthreads();   // previous tile fully consumed (also covers Qt on kt=0)
        // load K (transposed) and V (row-major) tiles
#pragma unroll
        for (int i = 0; i < 8; i++) {
            int lin = tid + i*256;
            int r = lin >> 5;
            int d = (lin & 31) * 4;
            float4 kv = *(const float4*)(Kg + base + (size_t)(k0 + r) * DD + d);
            Kt[(d+0)*68 + r] = kv.x;
            Kt[(d+1)*68 + r] = kv.y;
            Kt[(d+2)*68 + r] = kv.z;
            Kt[(d+3)*68 + r] = kv.w;
            float4 vv = *(const float4*)(V + base + (size_t)(k0 + r) * DD + d);
            *(float4*)&Vs[r*128 + d] = vv;
        }
        __syncthreads();

        // S = (Q*rscale) @ K^T for this tile: each thread 4x4
        float s[4][4];
#pragma unroll
        for (int i = 0; i < 4; i++)
#pragma unroll
            for (int j = 0; j < 4; j++) s[i][j] = 0.f;
#pragma unroll 8
        for (int d = 0; d < 128; d++) {
            float4 af = *(float4*)&Qt[d*68 + ty*4];
            float4 bf = *(float4*)&Kt[d*68 + tx*4];
            s[0][0] += af.x*bf.x; s[0][1] += af.x*bf.y; s[0][2] += af.x*bf.z; s[0][3] += af.x*bf.w;
            s[1][0] += af.y*bf.x; s[1][1] += af.y*bf.y; s[1][2] += af.y*bf.z; s[1][3] += af.y*bf.w;
            s[2][0] += af.z*bf.x; s[2][1] += af.z*bf.y; s[2][2] += af.z*bf.z; s[2][3] += af.z*bf.w;
            s[3][0] += af.w*bf.x; s[3][1] += af.w*bf.y; s[3][2] += af.w*bf.z; s[3][3] += af.w*bf.w;
        }
        bool diag = (kt == ntiles - 1);  // only the k0==q0 tile needs masking
#pragma unroll
        for (int i = 0; i < 4; i++) {
            int qi = ty*4 + i;
#pragma unroll
            for (int j = 0; j < 4; j++) {
                int kj = tx*4 + j;
                float val = s[i][j];
                if (diag && kj > qi) val = -1e30f;
                Ps[qi*68 + kj] = val;
            }
        }
        __syncthreads();

        // online softmax per row (64 rows on 64 threads)
        if (tid < 64) {
            int r = tid;
            float tm = -1e30f;
#pragma unroll 8
            for (int j = 0; j < 64; j++) tm = fmaxf(tm, Ps[r*68 + j]);
            float mo = mrow[r];
            float mn = fmaxf(mo, tm);
            float f  = __expf(mo - mn);
            float ps = 0.f;
#pragma unroll 8
            for (int j = 0; j < 64; j++) {
                float p = __expf(Ps[r*68 + j] - mn);
                Ps[r*68 + j] = p;
                ps += p;
            }
            lrow[r] = lrow[r]*f + ps;
            mrow[r] = mn;
            frow[r] = f;
        }
        __syncthreads();

        // rescale accumulators, then O += P @ V
        float fs[4];
#pragma unroll
        for (int i = 0; i < 4; i++) fs[i] = frow[ty*4 + i];
#pragma unroll
        for (int i = 0; i < 4; i++)
#pragma unroll
            for (int j = 0; j < 8; j++) acc[i][j] *= fs[i];
#pragma unroll 4
        for (int j = 0; j < 64; j++) {
            float p0 = Ps[(ty*4+0)*68 + j];
            float p1 = Ps[(ty*4+1)*68 + j];
            float p2 = Ps[(ty*4+2)*68 + j];
            float p3 = Ps[(ty*4+3)*68 + j];
            float4 v0 = *(float4*)&Vs[j*128 + tx*8];
            float4 v1 = *(float4*)&Vs[j*128 + tx*8 + 4];
            acc[0][0] += p0*v0.x; acc[0][1] += p0*v0.y; acc[0][2] += p0*v0.z; acc[0][3] += p0*v0.w;
            acc[0][4] += p0*v1.x; acc[0][5] += p0*v1.y; acc[0][6] += p0*v1.z; acc[0][7] += p0*v1.w;
            acc[1][0] += p1*v0.x; acc[1][1] += p1*v0.y; acc[1][2] += p1*v0.z; acc[1][3] += p1*v0.w;
            acc[1][4] += p1*v1.x; acc[1][5] += p1*v1.y; acc[1][6] += p1*v1.z; acc[1][7] += p1*v1.w;
            acc[2][0] += p2*v0.x; acc[2][1] += p2*v0.y; acc[2][2] += p2*v0.z; acc[2][3] += p2*v0.w;
            acc[2][4] += p2*v1.x; acc[2][5] += p2*v1.y; acc[2][6] += p2*v1.z; acc[2][7] += p2*v1.w;
            acc[3][0] += p3*v0.x; acc[3][1] += p3*v0.y; acc[3][2] += p3*v0.z; acc[3][3] += p3*v0.w;
            acc[3][4] += p3*v1.x; acc[3][5] += p3*v1.y; acc[3][6] += p3*v1.z; acc[3][7] += p3*v1.w;
        }
    }

    // write out ctx
#pragma unroll
    for (int i = 0; i < 4; i++) {
        int r = ty*4 + i;
        float inv = 1.0f / lrow[r];
        float4 o0, o1;
        o0.x = acc[i][0]*inv; o0.y = acc[i][1]*inv; o0.z = acc[i][2]*inv; o0.w = acc[i][3]*inv;
        o1.x = acc[i][4]*inv; o1.y = acc[i][5]*inv; o1.z = acc[i][6]*inv; o1.w = acc[i][7]*inv;
        float* op = O + base + (size_t)(q0 + r) * DD + tx*8;
        *(float4*)(op)     = o0;
        *(float4*)(op + 4) = o1;
    }
}

// ---------------- launch ----------------
extern "C" void kernel_launch(void* const* d_in, const int* in_sizes, int n_in,
                              void* d_out, int out_size) {
    const float* x    = (const float*)d_in[0];
    const float* Wq   = (const float*)d_in[1];
    const float* Wk   = (const float*)d_in[2];
    const float* Wv   = (const float*)d_in[3];
    const float* Wo   = (const float*)d_in[4];
    const float* bo   = (const float*)d_in[5];
    const float* ln1s = (const float*)d_in[6];
    const float* ln1b = (const float*)d_in[7];
    const float* ln2s = (const float*)d_in[8];
    const float* ln2b = (const float*)d_in[9];
    const float* W1   = (const float*)d_in[10];
    const float* b1   = (const float*)d_in[11];
    const float* W2   = (const float*)d_in[12];
    const float* b2   = (const float*)d_in[13];
    float* out = (float*)d_out;

    float *xn, *q, *k, *v, *ctx, *h, *ff;
    cudaGetSymbolAddress((void**)&xn,  g_xn);
    cudaGetSymbolAddress((void**)&q,   g_q);
    cudaGetSymbolAddress((void**)&k,   g_k);
    cudaGetSymbolAddress((void**)&v,   g_v);
    cudaGetSymbolAddress((void**)&ctx, g_ctx);
    cudaGetSymbolAddress((void**)&h,   g_h);
    cudaGetSymbolAddress((void**)&ff,  g_ff);

    cudaFuncSetAttribute(attn_kernel, cudaFuncAttributeMaxDynamicSharedMemorySize,
                         ATT_SMEM_BYTES);

    // 1) LN1
    ln_kernel<<<MROW, 256>>>(x, ln1s, ln1b, xn);
    // 2) QKV projections
    gemm_kernel<0><<<dim3(DD/128, MROW/128), 256>>>(xn, Wq, nullptr, nullptr, q, DD, DD);
    gemm_kernel<0><<<dim3(DD/128, MROW/128), 256>>>(xn, Wk, nullptr, nullptr, k, DD, DD);
    gemm_kernel<0><<<dim3(DD/128, MROW/128), 256>>>(xn, Wv, nullptr, nullptr, v, DD, DD);
    // 3) causal attention
    attn_kernel<<<dim3(SS/64, BB*HH), 256, ATT_SMEM_BYTES>>>(q, k, v, ctx);
    // 4) output projection + bias + residual
    gemm_kernel<1><<<dim3(DD/128, MROW/128), 256>>>(ctx, Wo, bo, x, h, DD, DD);
    // 5) LN2
    ln_kernel<<<MROW, 256>>>(h, ln2s, ln2b, xn);
    // 6) FFN up + GELU
    gemm_kernel<2><<<dim3(DFF/128, MROW/128), 256>>>(xn, W1, b1, nullptr, ff, DFF, DD);
    // 7) FFN down + bias + residual
    gemm_kernel<1><<<dim3(DD/128, MROW/128), 256>>>(ff, W2, b2, h, out, DD, DFF);
}

// round 4
// speedup vs baseline: 2.1718x; 2.1718x over previous
#include <cuda_runtime.h>
#include <math.h>
#include <stdint.h>

#define BB   2
#define SS   2048
#define DD   2048
#define HH   16
#define HD   128
#define DFF  8192
#define MROW 4096
#define EPSV 1e-5f

// ---------------- scratch ----------------
static __device__ float g_xn [(size_t)MROW*DD];
static __device__ float g_q  [(size_t)MROW*DD];
static __device__ float g_k  [(size_t)MROW*DD];
static __device__ float g_v  [(size_t)MROW*DD];
static __device__ float g_ctx[(size_t)MROW*DD];
static __device__ float g_h  [(size_t)MROW*DD];
static __device__ float g_ff [(size_t)MROW*DFF];

// ---------------- helpers ----------------
__device__ __forceinline__ uint32_t smem_u32(const void* p) {
    uint32_t a;
    asm("{ .reg .u64 t; cvta.to.shared.u64 t, %1; cvt.u32.u64 %0, t; }" : "=r"(a) : "l"(p));
    return a;
}
__device__ __forceinline__ void cp_async16(uint32_t s, const void* g) {
    asm volatile("cp.async.cg.shared.global [%0], [%1], 16;" :: "r"(s), "l"(g));
}
__device__ __forceinline__ void cp_commit() {
    asm volatile("cp.async.commit_group;" ::: "memory");
}
__device__ __forceinline__ void cp_wait2() {
    asm volatile("cp.async.wait_group 2;" ::: "memory");
}
__device__ __forceinline__ uint32_t f2tf32(float x) {
    uint32_t r;
    asm("cvt.rna.tf32.f32 %0, %1;" : "=r"(r) : "f"(x));
    return r;
}
__device__ __forceinline__ void mma_tf32(float* c, const uint32_t* a, const uint32_t* b) {
    asm volatile("mma.sync.aligned.m16n8k8.row.col.f32.tf32.tf32.f32 "
        "{%0,%1,%2,%3}, {%4,%5,%6,%7}, {%8,%9}, {%0,%1,%2,%3};"
        : "+f"(c[0]), "+f"(c[1]), "+f"(c[2]), "+f"(c[3])
        : "r"(a[0]), "r"(a[1]), "r"(a[2]), "r"(a[3]), "r"(b[0]), "r"(b[1]));
}
__device__ __forceinline__ float gelu_f(float x) {
    float x3 = x*x*x;
    return 0.5f * x * (1.0f + tanhf(0.79788456080286536f * (x + 0.044715f*x3)));
}

// ---------------- LayerNorm ----------------
__global__ __launch_bounds__(256)
void ln_kernel(const float* __restrict__ x, const float* __restrict__ sc,
               const float* __restrict__ sh, float* __restrict__ out) {
    int row = blockIdx.x;
    const float* xr = x + (size_t)row * DD;
    float v[8];
    float s = 0.f, sq = 0.f;
#pragma unroll
    for (int i = 0; i < 8; i++) {
        v[i] = xr[threadIdx.x + i*256];
        s += v[i]; sq += v[i]*v[i];
    }
    __shared__ float rs[8], rq[8];
    __shared__ float s_mean, s_rstd;
#pragma unroll
    for (int o = 16; o > 0; o >>= 1) {
        s  += __shfl_down_sync(0xFFFFFFFFu, s,  o);
        sq += __shfl_down_sync(0xFFFFFFFFu, sq, o);
    }
    int w = threadIdx.x >> 5;
    if ((threadIdx.x & 31) == 0) { rs[w] = s; rq[w] = sq; }
    __syncthreads();
    if (threadIdx.x == 0) {
        float ts = 0.f, tq = 0.f;
#pragma unroll
        for (int i = 0; i < 8; i++) { ts += rs[i]; tq += rq[i]; }
        float mean = ts * (1.0f/DD);
        s_mean = mean;
        s_rstd = rsqrtf(tq * (1.0f/DD) - mean*mean + EPSV);
    }
    __syncthreads();
    float mean = s_mean, rstd = s_rstd;
    float* orow = out + (size_t)row * DD;
#pragma unroll
    for (int i = 0; i < 8; i++) {
        int d = threadIdx.x + i*256;
        orow[d] = sc[d]*(v[i]-mean)*rstd + sh[d];
    }
}

// ---------------- TF32 tensor-core GEMM ----------------
// C[M,N] = A[M,K] @ B[K,N]; 128x128 tile, 8 warps (2M x 4N), warp 64x32.
// EPI 0: C=acc   EPI 1: C=acc+bias[n]+R[m,n]   EPI 2: C=gelu(acc+bias[n])
#define KSTEP   32
#define NSTG    3
#define A_ROWF  36                       // 32 + 4 pad floats
#define B_ROWF  132                      // 128 + 4 pad floats
#define A_BYTES (128*A_ROWF*4)           // 18432
#define B_BYTES (KSTEP*B_ROWF*4)         // 16896
#define STG_B   (A_BYTES + B_BYTES)      // 35328
#define G_SMEM  (NSTG*STG_B)             // 105984

template<int EPI>
__global__ __launch_bounds__(256, 2)
void mma_gemm(const float* __restrict__ A, const float* __restrict__ B,
              const float* __restrict__ bias, const float* __restrict__ R,
              float* __restrict__ C, int N, int K) {
    extern __shared__ char dsm[];
    const int tid = threadIdx.x;
    const int lane = tid & 31;
    const int wid = tid >> 5;
    const int warpM = wid & 1;           // 0..1
    const int warpN = wid >> 1;          // 0..3
    const int m0 = blockIdx.y * 128;
    const int n0 = blockIdx.x * 128;
    const uint32_t sb = smem_u32(dsm);

    float acc[4][4][4];                  // [mt][nt][4]
#pragma unroll
    for (int i = 0; i < 4; i++)
#pragma unroll
        for (int j = 0; j < 4; j++)
#pragma unroll
            for (int u = 0; u < 4; u++) acc[i][j][u] = 0.f;

    // load-index precompute
    const int ar = tid >> 1;             // A: 2 chunks/row handled over i-loop
    // A stage: 128 rows x 32 floats; chunk index = i*256+tid; r=idx/8, c=idx%8
    // B stage: 32 rows x 128 floats; r=idx/32, c=idx%32

    const int NT = K / KSTEP;
    (void)ar;

    auto load_stage = [&](int s, int kk) {
        uint32_t ab = sb + s*STG_B;
        uint32_t bb = ab + A_BYTES;
#pragma unroll
        for (int i = 0; i < 4; i++) {
            int idx = i*256 + tid;
            int r = idx >> 3, c = idx & 7;
            cp_async16(ab + r*(A_ROWF*4) + c*16,
                       A + (size_t)(m0 + r)*K + kk + c*4);
        }
#pragma unroll
        for (int i = 0; i < 4; i++) {
            int idx = i*256 + tid;
            int r = idx >> 5, c = idx & 31;
            cp_async16(bb + r*(B_ROWF*4) + c*16,
                       B + (size_t)(kk + r)*N + n0 + c*4);
        }
    };

    load_stage(0, 0); cp_commit();
    load_stage(1, KSTEP); cp_commit();

    const float* As_f = (const float*)dsm;
    for (int t = 0; t < NT; t++) {
        if (t + 2 < NT) load_stage((t+2)%NSTG, (t+2)*KSTEP);
        cp_commit();
        cp_wait2();
        __syncthreads();

        int s = t % NSTG;
        const float* Af = As_f + s*(STG_B/4);
        const float* Bf = Af + (A_BYTES/4);
        int arow = warpM*64 + (lane >> 2);
        int acol = lane & 3;
        int bcol = warpN*32 + (lane >> 2);
        int brow = lane & 3;
#pragma unroll
        for (int k8 = 0; k8 < 4; k8++) {
            int kb = k8*8;
            uint32_t afr[4][4];
#pragma unroll
            for (int mt = 0; mt < 4; mt++) {
                int r = arow + mt*16;
                afr[mt][0] = f2tf32(Af[(r  )*A_ROWF + kb + acol    ]);
                afr[mt][1] = f2tf32(Af[(r+8)*A_ROWF + kb + acol    ]);
                afr[mt][2] = f2tf32(Af[(r  )*A_ROWF + kb + acol + 4]);
                afr[mt][3] = f2tf32(Af[(r+8)*A_ROWF + kb + acol + 4]);
            }
            uint32_t bfr[4][2];
#pragma unroll
            for (int nt = 0; nt < 4; nt++) {
                int cc = bcol + nt*8;
                bfr[nt][0] = f2tf32(Bf[(kb + brow    )*B_ROWF + cc]);
                bfr[nt][1] = f2tf32(Bf[(kb + brow + 4)*B_ROWF + cc]);
            }
#pragma unroll
            for (int mt = 0; mt < 4; mt++)
#pragma unroll
                for (int nt = 0; nt < 4; nt++)
                    mma_tf32(acc[mt][nt], afr[mt], bfr[nt]);
        }
        __syncthreads();
    }

    // epilogue: rows m0+warpM*64+mt*16+{lane/4, lane/4+8}, cols n0+warpN*32+nt*8+2*(lane%4)
#pragma unroll
    for (int mt = 0; mt < 4; mt++) {
#pragma unroll
        for (int half = 0; half < 2; half++) {
            int m = m0 + warpM*64 + mt*16 + (lane >> 2) + half*8;
#pragma unroll
            for (int nt = 0; nt < 4; nt++) {
                int n = n0 + warpN*32 + nt*8 + 2*(lane & 3);
                float v0 = acc[mt][nt][half*2 + 0];
                float v1 = acc[mt][nt][half*2 + 1];
                if (EPI == 1) {
                    const float2 bb = *(const float2*)(bias + n);
                    const float2 rr = *(const float2*)(R + (size_t)m*N + n);
                    v0 += bb.x + rr.x;
                    v1 += bb.y + rr.y;
                } else if (EPI == 2) {
                    const float2 bb = *(const float2*)(bias + n);
                    v0 = gelu_f(v0 + bb.x);
                    v1 = gelu_f(v1 + bb.y);
                }
                float2 o; o.x = v0; o.y = v1;
                *(float2*)(C + (size_t)m*N + n) = o;
            }
        }
    }
}

// ---------------- causal flash attention (fp32 SIMT) ----------------
#define ATT_SMEM_FLOATS (128*68 + 128*68 + 64*128 + 64*68 + 3*64)
#define ATT_SMEM_BYTES  (ATT_SMEM_FLOATS * 4)

__global__ __launch_bounds__(256)
void attn_kernel(const float* __restrict__ Q, const float* __restrict__ Kg,
                 const float* __restrict__ V, float* __restrict__ O) {
    extern __shared__ float sm[];
    float* Qt   = sm;
    float* Kt   = Qt + 128*68;
    float* Vs   = Kt + 128*68;
    float* Ps   = Vs + 64*128;
    float* mrow = Ps + 64*68;
    float* lrow = mrow + 64;
    float* frow = lrow + 64;

    int tid = threadIdx.x;
    int tx = tid & 15, ty = tid >> 4;
    int q0 = blockIdx.x * 64;
    int b  = blockIdx.y >> 4;
    int h  = blockIdx.y & 15;
    const float rscale = 0.08838834764831845f;

    size_t base = ((size_t)b * SS) * DD + (size_t)h * HD;

#pragma unroll
    for (int i = 0; i < 8; i++) {
        int lin = tid + i*256;
        int r = lin >> 5;
        int d = (lin & 31) * 4;
        float4 qv = *(const float4*)(Q + base + (size_t)(q0 + r) * DD + d);
        Qt[(d+0)*68 + r] = qv.x * rscale;
        Qt[(d+1)*68 + r] = qv.y * rscale;
        Qt[(d+2)*68 + r] = qv.z * rscale;
        Qt[(d+3)*68 + r] = qv.w * rscale;
    }
    if (tid < 64) { mrow[tid] = -1e30f; lrow[tid] = 0.f; }

    float acc[4][8];
#pragma unroll
    for (int i = 0; i < 4; i++)
#pragma unroll
        for (int j = 0; j < 8; j++) acc[i][j] = 0.f;

    int ntiles = (q0 >> 6) + 1;
    for (int kt = 0; kt < ntiles; kt++) {
        int k0 = kt * 64;
        __syncthreads();
#pragma unroll
        for (int i = 0; i < 8; i++) {
            int lin = tid + i*256;
            int r = lin >> 5;
            int d = (lin & 31) * 4;
            float4 kv = *(const float4*)(Kg + base + (size_t)(k0 + r) * DD + d);
            Kt[(d+0)*68 + r] = kv.x;
            Kt[(d+1)*68 + r] = kv.y;
            Kt[(d+2)*68 + r] = kv.z;
            Kt[(d+3)*68 + r] = kv.w;
            float4 vv = *(const float4*)(V + base + (size_t)(k0 + r) * DD + d);
            *(float4*)&Vs[r*128 + d] = vv;
        }
        __syncthreads();

        float s4[4][4];
#pragma unroll
        for (int i = 0; i < 4; i++)
#pragma unroll
            for (int j = 0; j < 4; j++) s4[i][j] = 0.f;
#pragma unroll 8
        for (int d = 0; d < 128; d++) {
            float4 af = *(float4*)&Qt[d*68 + ty*4];
            float4 bf = *(float4*)&Kt[d*68 + tx*4];
            s4[0][0] += af.x*bf.x; s4[0][1] += af.x*bf.y; s4[0][2] += af.x*bf.z; s4[0][3] += af.x*bf.w;
            s4[1][0] += af.y*bf.x; s4[1][1] += af.y*bf.y; s4[1][2] += af.y*bf.z; s4[1][3] += af.y*bf.w;
            s4[2][0] += af.z*bf.x; s4[2][1] += af.z*bf.y; s4[2][2] += af.z*bf.z; s4[2][3] += af.z*bf.w;
            s4[3][0] += af.w*bf.x; s4[3][1] += af.w*bf.y; s4[3][2] += af.w*bf.z; s4[3][3] += af.w*bf.w;
        }
        bool diag = (kt == ntiles - 1);
#pragma unroll
        for (int i = 0; i < 4; i++) {
            int qi = ty*4 + i;
#pragma unroll
            for (int j = 0; j < 4; j++) {
                int kj = tx*4 + j;
                float val = s4[i][j];
                if (diag && kj > qi) val = -1e30f;
                Ps[qi*68 + kj] = val;
            }
        }
        __syncthreads();

        if (tid < 64) {
            int r = tid;
            float tm = -1e30f;
#pragma unroll 8
            for (int j = 0; j < 64; j++) tm = fmaxf(tm, Ps[r*68 + j]);
            float mo = mrow[r];
            float mn = fmaxf(mo, tm);
            float f  = __expf(mo - mn);
            float ps = 0.f;
#pragma unroll 8
            for (int j = 0; j < 64; j++) {
                float p = __expf(Ps[r*68 + j] - mn);
                Ps[r*68 + j] = p;
                ps += p;
            }
            lrow[r] = lrow[r]*f + ps;
            mrow[r] = mn;
            frow[r] = f;
        }
        __syncthreads();

        float fs[4];
#pragma unroll
        for (int i = 0; i < 4; i++) fs[i] = frow[ty*4 + i];
#pragma unroll
        for (int i = 0; i < 4; i++)
#pragma unroll
            for (int j = 0; j < 8; j++) acc[i][j] *= fs[i];
#pragma unroll 4
        for (int j = 0; j < 64; j++) {
            float p0 = Ps[(ty*4+0)*68 + j];
            float p1 = Ps[(ty*4+1)*68 + j];
            float p2 = Ps[(ty*4+2)*68 + j];
            float p3 = Ps[(ty*4+3)*68 + j];
            float4 v0 = *(float4*)&Vs[j*128 + tx*8];
            float4 v1 = *(float4*)&Vs[j*128 + tx*8 + 4];
            acc[0][0] += p0*v0.x; acc[0][1] += p0*v0.y; acc[0][2] += p0*v0.z; acc[0][3] += p0*v0.w;
            acc[0][4] += p0*v1.x; acc[0][5] += p0*v1.y; acc[0][6] += p0*v1.z; acc[0][7] += p0*v1.w;
            acc[1][0] += p1*v0.x; acc[1][1] += p1*v0.y; acc[1][2] += p1*v0.z; acc[1][3] += p1*v0.w;
            acc[1][4] += p1*v1.x; acc[1][5] += p1*v1.y; acc[1][6] += p1*v1.z; acc[1][7] += p1*v1.w;
            acc[2][0] += p2*v0.x; acc[2][1] += p2*v0.y; acc[2][2] += p2*v0.z; acc[2][3] += p2*v0.w;
            acc[2][4] += p2*v1.x; acc[2][5] += p2*v1.y; acc[2][6] += p2*v1.z; acc[2][7] += p2*v1.w;
            acc[3][0] += p3*v0.x; acc[3][1] += p3*v0.y; acc[3][2] += p3*v0.z; acc[3][3] += p3*v0.w;
            acc[3][4] += p3*v1.x; acc[3][5] += p3*v1.y; acc[3][6] += p3*v1.z; acc[3][7] += p3*v1.w;
        }
    }

#pragma unroll
    for (int i = 0; i < 4; i++) {
        int r = ty*4 + i;
        float inv = 1.0f / lrow[r];
        float4 o0, o1;
        o0.x = acc[i][0]*inv; o0.y = acc[i][1]*inv; o0.z = acc[i][2]*inv; o0.w = acc[i][3]*inv;
        o1.x = acc[i][4]*inv; o1.y = acc[i][5]*inv; o1.z = acc[i][6]*inv; o1.w = acc[i][7]*inv;
        float* op = O + base + (size_t)(q0 + r) * DD + tx*8;
        *(float4*)(op)     = o0;
        *(float4*)(op + 4) = o1;
    }
}

// ---------------- launch ----------------
extern "C" void kernel_launch(void* const* d_in, const int* in_sizes, int n_in,
                              void* d_out, int out_size) {
    const float* x    = (const float*)d_in[0];
    const float* Wq   = (const float*)d_in[1];
    const float* Wk   = (const float*)d_in[2];
    const float* Wv   = (const float*)d_in[3];
    const float* Wo   = (const float*)d_in[4];
    const float* bo   = (const float*)d_in[5];
    const float* ln1s = (const float*)d_in[6];
    const float* ln1b = (const float*)d_in[7];
    const float* ln2s = (const float*)d_in[8];
    const float* ln2b = (const float*)d_in[9];
    const float* W1   = (const float*)d_in[10];
    const float* b1   = (const float*)d_in[11];
    const float* W2   = (const float*)d_in[12];
    const float* b2   = (const float*)d_in[13];
    float* out = (float*)d_out;

    float *xn, *q, *k, *v, *ctx, *h, *ff;
    cudaGetSymbolAddress((void**)&xn,  g_xn);
    cudaGetSymbolAddress((void**)&q,   g_q);
    cudaGetSymbolAddress((void**)&k,   g_k);
    cudaGetSymbolAddress((void**)&v,   g_v);
    cudaGetSymbolAddress((void**)&ctx, g_ctx);
    cudaGetSymbolAddress((void**)&h,   g_h);
    cudaGetSymbolAddress((void**)&ff,  g_ff);

    cudaFuncSetAttribute(attn_kernel, cudaFuncAttributeMaxDynamicSharedMemorySize, ATT_SMEM_BYTES);
    cudaFuncSetAttribute(mma_gemm<0>, cudaFuncAttributeMaxDynamicSharedMemorySize, G_SMEM);
    cudaFuncSetAttribute(mma_gemm<1>, cudaFuncAttributeMaxDynamicSharedMemorySize, G_SMEM);
    cudaFuncSetAttribute(mma_gemm<2>, cudaFuncAttributeMaxDynamicSharedMemorySize, G_SMEM);

    // 1) LN1
    ln_kernel<<<MROW, 256>>>(x, ln1s, ln1b, xn);
    // 2) QKV projections (TF32 tensor cores)
    mma_gemm<0><<<dim3(DD/128, MROW/128), 256, G_SMEM>>>(xn, Wq, nullptr, nullptr, q, DD, DD);
    mma_gemm<0><<<dim3(DD/128, MROW/128), 256, G_SMEM>>>(xn, Wk, nullptr, nullptr, k, DD, DD);
    mma_gemm<0><<<dim3(DD/128, MROW/128), 256, G_SMEM>>>(xn, Wv, nullptr, nullptr, v, DD, DD);
    // 3) causal attention
    attn_kernel<<<dim3(SS/64, BB*HH), 256, ATT_SMEM_BYTES>>>(q, k, v, ctx);
    // 4) output projection + bias + residual
    mma_gemm<1><<<dim3(DD/128, MROW/128), 256, G_SMEM>>>(ctx, Wo, bo, x, h, DD, DD);
    // 5) LN2
    ln_kernel<<<MROW, 256>>>(h, ln2s, ln2b, xn);
    // 6) FFN up + GELU
    mma_gemm<2><<<dim3(DFF/128, MROW/128), 256, G_SMEM>>>(xn, W1, b1, nullptr, ff, DFF, DD);
    // 7) FFN down + bias + residual
    mma_gemm<1><<<dim3(DD/128, MROW/128), 256, G_SMEM>>>(ff, W2, b2, h, out, DD, DFF);
}

// round 5
// speedup vs baseline: 2.4397x; 1.1234x over previous
#include <cuda_runtime.h>
#include <math.h>
#include <stdint.h>

#define BB   2
#define SS   2048
#define DD   2048
#define HH   16
#define HD   128
#define DFF  8192
#define MROW 4096
#define EPSV 1e-5f

// ---------------- scratch ----------------
static __device__ float g_xn [(size_t)MROW*DD];
static __device__ float g_q  [(size_t)MROW*DD];
static __device__ float g_k  [(size_t)MROW*DD];
static __device__ float g_v  [(size_t)MROW*DD];
static __device__ float g_ctx[(size_t)MROW*DD];
static __device__ float g_h  [(size_t)MROW*DD];
static __device__ float g_ff [(size_t)MROW*DFF];
// rounded (tf32) weight copies
static __device__ float g_wq [(size_t)DD*DD];
static __device__ float g_wk [(size_t)DD*DD];
static __device__ float g_wv [(size_t)DD*DD];
static __device__ float g_wo [(size_t)DD*DD];
static __device__ float g_w1 [(size_t)DD*DFF];
static __device__ float g_w2 [(size_t)DFF*DD];

// ---------------- helpers ----------------
__device__ __forceinline__ uint32_t smem_u32(const void* p) {
    uint32_t a;
    asm("{ .reg .u64 t; cvta.to.shared.u64 t, %1; cvt.u32.u64 %0, t; }" : "=r"(a) : "l"(p));
    return a;
}
__device__ __forceinline__ void cp_async16(uint32_t s, const void* g) {
    asm volatile("cp.async.cg.shared.global [%0], [%1], 16;" :: "r"(s), "l"(g));
}
__device__ __forceinline__ void cp_commit() {
    asm volatile("cp.async.commit_group;" ::: "memory");
}
__device__ __forceinline__ void cp_wait2() {
    asm volatile("cp.async.wait_group 2;" ::: "memory");
}
__device__ __forceinline__ float rtf32(float x) {
    uint32_t r;
    asm("cvt.rna.tf32.f32 %0, %1;" : "=r"(r) : "f"(x));
    return __uint_as_float(r);
}
__device__ __forceinline__ void mma_tf32(float* c, const uint32_t* a, const uint32_t* b) {
    asm volatile("mma.sync.aligned.m16n8k8.row.col.f32.tf32.tf32.f32 "
        "{%0,%1,%2,%3}, {%4,%5,%6,%7}, {%8,%9}, {%0,%1,%2,%3};"
        : "+f"(c[0]), "+f"(c[1]), "+f"(c[2]), "+f"(c[3])
        : "r"(a[0]), "r"(a[1]), "r"(a[2]), "r"(a[3]), "r"(b[0]), "r"(b[1]));
}
__device__ __forceinline__ float gelu_f(float x) {
    float x3 = x*x*x;
    return 0.5f * x * (1.0f + tanhf(0.79788456080286536f * (x + 0.044715f*x3)));
}

// ---------------- TF32 pre-round (elementwise, float4) ----------------
__global__ __launch_bounds__(256)
void round_tf32_kernel(const float* __restrict__ src, float* __restrict__ dst, int n4) {
    int i = blockIdx.x*256 + threadIdx.x;
    if (i < n4) {
        float4 v = ((const float4*)src)[i];
        v.x = rtf32(v.x); v.y = rtf32(v.y); v.z = rtf32(v.z); v.w = rtf32(v.w);
        ((float4*)dst)[i] = v;
    }
}

// ---------------- LayerNorm (writes tf32-rounded output) ----------------
__global__ __launch_bounds__(256)
void ln_kernel(const float* __restrict__ x, const float* __restrict__ sc,
               const float* __restrict__ sh, float* __restrict__ out) {
    int row = blockIdx.x;
    const float* xr = x + (size_t)row * DD;
    float v[8];
    float s = 0.f, sq = 0.f;
#pragma unroll
    for (int i = 0; i < 8; i++) {
        v[i] = xr[threadIdx.x + i*256];
        s += v[i]; sq += v[i]*v[i];
    }
    __shared__ float rs[8], rq[8];
    __shared__ float s_mean, s_rstd;
#pragma unroll
    for (int o = 16; o > 0; o >>= 1) {
        s  += __shfl_down_sync(0xFFFFFFFFu, s,  o);
        sq += __shfl_down_sync(0xFFFFFFFFu, sq, o);
    }
    int w = threadIdx.x >> 5;
    if ((threadIdx.x & 31) == 0) { rs[w] = s; rq[w] = sq; }
    __syncthreads();
    if (threadIdx.x == 0) {
        float ts = 0.f, tq = 0.f;
#pragma unroll
        for (int i = 0; i < 8; i++) { ts += rs[i]; tq += rq[i]; }
        float mean = ts * (1.0f/DD);
        s_mean = mean;
        s_rstd = rsqrtf(tq * (1.0f/DD) - mean*mean + EPSV);
    }
    __syncthreads();
    float mean = s_mean, rstd = s_rstd;
    float* orow = out + (size_t)row * DD;
#pragma unroll
    for (int i = 0; i < 8; i++) {
        int d = threadIdx.x + i*256;
        orow[d] = rtf32(sc[d]*(v[i]-mean)*rstd + sh[d]);
    }
}

// ---------------- TF32 tensor-core GEMM ----------------
// Inputs must already be tf32-rounded. 128x128 tile, 8 warps (2M x 4N).
// EPI 0: C=acc   EPI 1: C=acc+bias[n]+R[m,n]   EPI 2: C=rtf32(gelu(acc+bias[n]))
#define KSTEP   32
#define NSTG    3
#define A_ROWF  36
#define B_ROWF  136
#define A_BYTES (128*A_ROWF*4)           // 18432
#define B_BYTES (KSTEP*B_ROWF*4)         // 17408
#define STG_B   (A_BYTES + B_BYTES)      // 35840
#define G_SMEM  (NSTG*STG_B)             // 107520

template<int EPI>
__global__ __launch_bounds__(256, 2)
void mma_gemm(const float* __restrict__ A, const float* __restrict__ B,
              const float* __restrict__ bias, const float* __restrict__ R,
              float* __restrict__ C, int N, int K) {
    extern __shared__ char dsm[];
    const int tid = threadIdx.x;
    const int lane = tid & 31;
    const int wid = tid >> 5;
    const int warpM = wid & 1;
    const int warpN = wid >> 1;
    const int m0 = blockIdx.y * 128;
    const int n0 = blockIdx.x * 128;
    const uint32_t sb = smem_u32(dsm);

    float acc[4][4][4];
#pragma unroll
    for (int i = 0; i < 4; i++)
#pragma unroll
        for (int j = 0; j < 4; j++)
#pragma unroll
            for (int u = 0; u < 4; u++) acc[i][j][u] = 0.f;

    const int NT = K / KSTEP;

    auto load_stage = [&](int s, int kk) {
        uint32_t ab = sb + s*STG_B;
        uint32_t bbase = ab + A_BYTES;
#pragma unroll
        for (int i = 0; i < 4; i++) {
            int idx = i*256 + tid;
            int r = idx >> 3, c = idx & 7;
            cp_async16(ab + r*(A_ROWF*4) + c*16,
                       A + (size_t)(m0 + r)*K + kk + c*4);
        }
#pragma unroll
        for (int i = 0; i < 4; i++) {
            int idx = i*256 + tid;
            int r = idx >> 5, c = idx & 31;
            cp_async16(bbase + r*(B_ROWF*4) + c*16,
                       B + (size_t)(kk + r)*N + n0 + c*4);
        }
    };

    load_stage(0, 0); cp_commit();
    load_stage(1, KSTEP); cp_commit();

    const uint32_t* As_u = (const uint32_t*)dsm;
    const int arow = warpM*64 + (lane >> 2);
    const int acol = lane & 3;
    const int bcol = warpN*32 + (lane >> 2);
    const int brow = lane & 3;

    for (int t = 0; t < NT; t++) {
        if (t + 2 < NT) load_stage((t+2)%NSTG, (t+2)*KSTEP);
        cp_commit();
        cp_wait2();
        __syncthreads();

        int s = t % NSTG;
        const uint32_t* Au = As_u + s*(STG_B/4);
        const uint32_t* Bu = Au + (A_BYTES/4);
#pragma unroll
        for (int k8 = 0; k8 < 4; k8++) {
            int kb = k8*8;
            uint32_t afr[4][4];
#pragma unroll
            for (int mt = 0; mt < 4; mt++) {
                int r = arow + mt*16;
                afr[mt][0] = Au[(r  )*A_ROWF + kb + acol    ];
                afr[mt][1] = Au[(r+8)*A_ROWF + kb + acol    ];
                afr[mt][2] = Au[(r  )*A_ROWF + kb + acol + 4];
                afr[mt][3] = Au[(r+8)*A_ROWF + kb + acol + 4];
            }
            uint32_t bfr[4][2];
#pragma unroll
            for (int nt = 0; nt < 4; nt++) {
                int cc = bcol + nt*8;
                bfr[nt][0] = Bu[(kb + brow    )*B_ROWF + cc];
                bfr[nt][1] = Bu[(kb + brow + 4)*B_ROWF + cc];
            }
#pragma unroll
            for (int mt = 0; mt < 4; mt++)
#pragma unroll
                for (int nt = 0; nt < 4; nt++)
                    mma_tf32(acc[mt][nt], afr[mt], bfr[nt]);
        }
        __syncthreads();
    }

#pragma unroll
    for (int mt = 0; mt < 4; mt++) {
#pragma unroll
        for (int half = 0; half < 2; half++) {
            int m = m0 + warpM*64 + mt*16 + (lane >> 2) + half*8;
#pragma unroll
            for (int nt = 0; nt < 4; nt++) {
                int n = n0 + warpN*32 + nt*8 + 2*(lane & 3);
                float v0 = acc[mt][nt][half*2 + 0];
                float v1 = acc[mt][nt][half*2 + 1];
                if (EPI == 1) {
                    const float2 bb = *(const float2*)(bias + n);
                    const float2 rr = *(const float2*)(R + (size_t)m*N + n);
                    v0 += bb.x + rr.x;
                    v1 += bb.y + rr.y;
                } else if (EPI == 2) {
                    const float2 bb = *(const float2*)(bias + n);
                    v0 = rtf32(gelu_f(v0 + bb.x));
                    v1 = rtf32(gelu_f(v1 + bb.y));
                }
                float2 o; o.x = v0; o.y = v1;
                *(float2*)(C + (size_t)m*N + n) = o;
            }
        }
    }
}

// ---------------- causal flash attention (fp32 SIMT) ----------------
#define ATT_SMEM_FLOATS (128*68 + 128*68 + 64*128 + 64*68 + 3*64)
#define ATT_SMEM_BYTES  (ATT_SMEM_FLOATS * 4)

__global__ __launch_bounds__(256)
void attn_kernel(const float* __restrict__ Q, const float* __restrict__ Kg,
                 const float* __restrict__ V, float* __restrict__ O) {
    extern __shared__ float sm[];
    float* Qt   = sm;
    float* Kt   = Qt + 128*68;
    float* Vs   = Kt + 128*68;
    float* Ps   = Vs + 64*128;
    float* mrow = Ps + 64*68;
    float* lrow = mrow + 64;
    float* frow = lrow + 64;

    int tid = threadIdx.x;
    int tx = tid & 15, ty = tid >> 4;
    int q0 = blockIdx.x * 64;
    int b  = blockIdx.y >> 4;
    int h  = blockIdx.y & 15;
    const float rscale = 0.08838834764831845f;

    size_t base = ((size_t)b * SS) * DD + (size_t)h * HD;

#pragma unroll
    for (int i = 0; i < 8; i++) {
        int lin = tid + i*256;
        int r = lin >> 5;
        int d = (lin & 31) * 4;
        float4 qv = *(const float4*)(Q + base + (size_t)(q0 + r) * DD + d);
        Qt[(d+0)*68 + r] = qv.x * rscale;
        Qt[(d+1)*68 + r] = qv.y * rscale;
        Qt[(d+2)*68 + r] = qv.z * rscale;
        Qt[(d+3)*68 + r] = qv.w * rscale;
    }
    if (tid < 64) { mrow[tid] = -1e30f; lrow[tid] = 0.f; }

    float acc[4][8];
#pragma unroll
    for (int i = 0; i < 4; i++)
#pragma unroll
        for (int j = 0; j < 8; j++) acc[i][j] = 0.f;

    int ntiles = (q0 >> 6) + 1;
    for (int kt = 0; kt < ntiles; kt++) {
        int k0 = kt * 64;
        __syncthreads();
#pragma unroll
        for (int i = 0; i < 8; i++) {
            int lin = tid + i*256;
            int r = lin >> 5;
            int d = (lin & 31) * 4;
            float4 kv = *(const float4*)(Kg + base + (size_t)(k0 + r) * DD + d);
            Kt[(d+0)*68 + r] = kv.x;
            Kt[(d+1)*68 + r] = kv.y;
            Kt[(d+2)*68 + r] = kv.z;
            Kt[(d+3)*68 + r] = kv.w;
            float4 vv = *(const float4*)(V + base + (size_t)(k0 + r) * DD + d);
            *(float4*)&Vs[r*128 + d] = vv;
        }
        __syncthreads();

        float s4[4][4];
#pragma unroll
        for (int i = 0; i < 4; i++)
#pragma unroll
            for (int j = 0; j < 4; j++) s4[i][j] = 0.f;
#pragma unroll 8
        for (int d = 0; d < 128; d++) {
            float4 af = *(float4*)&Qt[d*68 + ty*4];
            float4 bf = *(float4*)&Kt[d*68 + tx*4];
            s4[0][0] += af.x*bf.x; s4[0][1] += af.x*bf.y; s4[0][2] += af.x*bf.z; s4[0][3] += af.x*bf.w;
            s4[1][0] += af.y*bf.x; s4[1][1] += af.y*bf.y; s4[1][2] += af.y*bf.z; s4[1][3] += af.y*bf.w;
            s4[2][0] += af.z*bf.x; s4[2][1] += af.z*bf.y; s4[2][2] += af.z*bf.z; s4[2][3] += af.z*bf.w;
            s4[3][0] += af.w*bf.x; s4[3][1] += af.w*bf.y; s4[3][2] += af.w*bf.z; s4[3][3] += af.w*bf.w;
        }
        bool diag = (kt == ntiles - 1);
#pragma unroll
        for (int i = 0; i < 4; i++) {
            int qi = ty*4 + i;
#pragma unroll
            for (int j = 0; j < 4; j++) {
                int kj = tx*4 + j;
                float val = s4[i][j];
                if (diag && kj > qi) val = -1e30f;
                Ps[qi*68 + kj] = val;
            }
        }
        __syncthreads();

        if (tid < 64) {
            int r = tid;
            float tm = -1e30f;
#pragma unroll 8
            for (int j = 0; j < 64; j++) tm = fmaxf(tm, Ps[r*68 + j]);
            float mo = mrow[r];
            float mn = fmaxf(mo, tm);
            float f  = __expf(mo - mn);
            float ps = 0.f;
#pragma unroll 8
            for (int j = 0; j < 64; j++) {
                float p = __expf(Ps[r*68 + j] - mn);
                Ps[r*68 + j] = p;
                ps += p;
            }
            lrow[r] = lrow[r]*f + ps;
            mrow[r] = mn;
            frow[r] = f;
        }
        __syncthreads();

        float fs[4];
#pragma unroll
        for (int i = 0; i < 4; i++) fs[i] = frow[ty*4 + i];
#pragma unroll
        for (int i = 0; i < 4; i++)
#pragma unroll
            for (int j = 0; j < 8; j++) acc[i][j] *= fs[i];
#pragma unroll 4
        for (int j = 0; j < 64; j++) {
            float p0 = Ps[(ty*4+0)*68 + j];
            float p1 = Ps[(ty*4+1)*68 + j];
            float p2 = Ps[(ty*4+2)*68 + j];
            float p3 = Ps[(ty*4+3)*68 + j];
            float4 v0 = *(float4*)&Vs[j*128 + tx*8];
            float4 v1 = *(float4*)&Vs[j*128 + tx*8 + 4];
            acc[0][0] += p0*v0.x; acc[0][1] += p0*v0.y; acc[0][2] += p0*v0.z; acc[0][3] += p0*v0.w;
            acc[0][4] += p0*v1.x; acc[0][5] += p0*v1.y; acc[0][6] += p0*v1.z; acc[0][7] += p0*v1.w;
            acc[1][0] += p1*v0.x; acc[1][1] += p1*v0.y; acc[1][2] += p1*v0.z; acc[1][3] += p1*v0.w;
            acc[1][4] += p1*v1.x; acc[1][5] += p1*v1.y; acc[1][6] += p1*v1.z; acc[1][7] += p1*v1.w;
            acc[2][0] += p2*v0.x; acc[2][1] += p2*v0.y; acc[2][2] += p2*v0.z; acc[2][3] += p2*v0.w;
            acc[2][4] += p2*v1.x; acc[2][5] += p2*v1.y; acc[2][6] += p2*v1.z; acc[2][7] += p2*v1.w;
            acc[3][0] += p3*v0.x; acc[3][1] += p3*v0.y; acc[3][2] += p3*v0.z; acc[3][3] += p3*v0.w;
            acc[3][4] += p3*v1.x; acc[3][5] += p3*v1.y; acc[3][6] += p3*v1.z; acc[3][7] += p3*v1.w;
        }
    }

#pragma unroll
    for (int i = 0; i < 4; i++) {
        int r = ty*4 + i;
        float inv = 1.0f / lrow[r];
        float4 o0, o1;
        o0.x = rtf32(acc[i][0]*inv); o0.y = rtf32(acc[i][1]*inv);
        o0.z = rtf32(acc[i][2]*inv); o0.w = rtf32(acc[i][3]*inv);
        o1.x = rtf32(acc[i][4]*inv); o1.y = rtf32(acc[i][5]*inv);
        o1.z = rtf32(acc[i][6]*inv); o1.w = rtf32(acc[i][7]*inv);
        float* op = O + base + (size_t)(q0 + r) * DD + tx*8;
        *(float4*)(op)     = o0;
        *(float4*)(op + 4) = o1;
    }
}

// ---------------- launch ----------------
extern "C" void kernel_launch(void* const* d_in, const int* in_sizes, int n_in,
                              void* d_out, int out_size) {
    const float* x    = (const float*)d_in[0];
    const float* Wq   = (const float*)d_in[1];
    const float* Wk   = (const float*)d_in[2];
    const float* Wv   = (const float*)d_in[3];
    const float* Wo   = (const float*)d_in[4];
    const float* bo   = (const float*)d_in[5];
    const float* ln1s = (const float*)d_in[6];
    const float* ln1b = (const float*)d_in[7];
    const float* ln2s = (const float*)d_in[8];
    const float* ln2b = (const float*)d_in[9];
    const float* W1   = (const float*)d_in[10];
    const float* b1   = (const float*)d_in[11];
    const float* W2   = (const float*)d_in[12];
    const float* b2   = (const float*)d_in[13];
    float* out = (float*)d_out;

    float *xn, *q, *k, *v, *ctx, *h, *ff;
    float *wq, *wk, *wv, *wo, *w1, *w2;
    cudaGetSymbolAddress((void**)&xn,  g_xn);
    cudaGetSymbolAddress((void**)&q,   g_q);
    cudaGetSymbolAddress((void**)&k,   g_k);
    cudaGetSymbolAddress((void**)&v,   g_v);
    cudaGetSymbolAddress((void**)&ctx, g_ctx);
    cudaGetSymbolAddress((void**)&h,   g_h);
    cudaGetSymbolAddress((void**)&ff,  g_ff);
    cudaGetSymbolAddress((void**)&wq,  g_wq);
    cudaGetSymbolAddress((void**)&wk,  g_wk);
    cudaGetSymbolAddress((void**)&wv,  g_wv);
    cudaGetSymbolAddress((void**)&wo,  g_wo);
    cudaGetSymbolAddress((void**)&w1,  g_w1);
    cudaGetSymbolAddress((void**)&w2,  g_w2);

    cudaFuncSetAttribute(attn_kernel, cudaFuncAttributeMaxDynamicSharedMemorySize, ATT_SMEM_BYTES);
    cudaFuncSetAttribute(mma_gemm<0>, cudaFuncAttributeMaxDynamicSharedMemorySize, G_SMEM);
    cudaFuncSetAttribute(mma_gemm<1>, cudaFuncAttributeMaxDynamicSharedMemorySize, G_SMEM);
    cudaFuncSetAttribute(mma_gemm<2>, cudaFuncAttributeMaxDynamicSharedMemorySize, G_SMEM);

    // 0) pre-round weights to tf32
    const int n4a = DD*DD/4, n4b = DD*DFF/4;
    round_tf32_kernel<<<(n4a+255)/256, 256>>>(Wq, wq, n4a);
    round_tf32_kernel<<<(n4a+255)/256, 256>>>(Wk, wk, n4a);
    round_tf32_kernel<<<(n4a+255)/256, 256>>>(Wv, wv, n4a);
    round_tf32_kernel<<<(n4a+255)/256, 256>>>(Wo, wo, n4a);
    round_tf32_kernel<<<(n4b+255)/256, 256>>>(W1, w1, n4b);
    round_tf32_kernel<<<(n4b+255)/256, 256>>>(W2, w2, n4b);

    // 1) LN1 (tf32-rounded output)
    ln_kernel<<<MROW, 256>>>(x, ln1s, ln1b, xn);
    // 2) QKV projections
    mma_gemm<0><<<dim3(DD/128, MROW/128), 256, G_SMEM>>>(xn, wq, nullptr, nullptr, q, DD, DD);
    mma_gemm<0><<<dim3(DD/128, MROW/128), 256, G_SMEM>>>(xn, wk, nullptr, nullptr, k, DD, DD);
    mma_gemm<0><<<dim3(DD/128, MROW/128), 256, G_SMEM>>>(xn, wv, nullptr, nullptr, v, DD, DD);
    // 3) causal attention (ctx tf32-rounded)
    attn_kernel<<<dim3(SS/64, BB*HH), 256, ATT_SMEM_BYTES>>>(q, k, v, ctx);
    // 4) output projection + bias + residual
    mma_gemm<1><<<dim3(DD/128, MROW/128), 256, G_SMEM>>>(ctx, wo, bo, x, h, DD, DD);
    // 5) LN2 (tf32-rounded output)
    ln_kernel<<<MROW, 256>>>(h, ln2s, ln2b, xn);
    // 6) FFN up + GELU (tf32-rounded output)
    mma_gemm<2><<<dim3(DFF/128, MROW/128), 256, G_SMEM>>>(xn, w1, b1, nullptr, ff, DFF, DD);
    // 7) FFN down + bias + residual
    mma_gemm<1><<<dim3(DD/128, MROW/128), 256, G_SMEM>>>(ff, w2, b2, h, out, DD, DFF);
}

// round 6
// speedup vs baseline: 3.5273x; 1.4458x over previous
#include <cuda_runtime.h>
#include <math.h>
#include <stdint.h>

#define BB   2
#define SS   2048
#define DD   2048
#define HH   16
#define HD   128
#define DFF  8192
#define MROW 4096
#define EPSV 1e-5f

// ---------------- scratch ----------------
static __device__ float g_xn [(size_t)MROW*DD];
static __device__ float g_q  [(size_t)MROW*DD];
static __device__ float g_k  [(size_t)MROW*DD];
static __device__ float g_v  [(size_t)MROW*DD];
static __device__ float g_ctx[(size_t)MROW*DD];
static __device__ float g_h  [(size_t)MROW*DD];
static __device__ float g_ff [(size_t)MROW*DFF];
static __device__ float g_wq [(size_t)DD*DD];
static __device__ float g_wk [(size_t)DD*DD];
static __device__ float g_wv [(size_t)DD*DD];
static __device__ float g_wo [(size_t)DD*DD];
static __device__ float g_w1 [(size_t)DD*DFF];
static __device__ float g_w2 [(size_t)DFF*DD];

// ---------------- helpers ----------------
__device__ __forceinline__ uint32_t smem_u32(const void* p) {
    uint32_t a;
    asm("{ .reg .u64 t; cvta.to.shared.u64 t, %1; cvt.u32.u64 %0, t; }" : "=r"(a) : "l"(p));
    return a;
}
__device__ __forceinline__ void cp_async16(uint32_t s, const void* g) {
    asm volatile("cp.async.cg.shared.global [%0], [%1], 16;" :: "r"(s), "l"(g));
}
__device__ __forceinline__ void cp_commit() {
    asm volatile("cp.async.commit_group;" ::: "memory");
}
__device__ __forceinline__ void cp_wait1() {
    asm volatile("cp.async.wait_group 1;" ::: "memory");
}
__device__ __forceinline__ float rtf32(float x) {
    uint32_t r;
    asm("cvt.rna.tf32.f32 %0, %1;" : "=r"(r) : "f"(x));
    return __uint_as_float(r);
}
__device__ __forceinline__ void mma_tf32(float* c, const uint32_t* a, const uint32_t* b) {
    asm volatile("mma.sync.aligned.m16n8k8.row.col.f32.tf32.tf32.f32 "
        "{%0,%1,%2,%3}, {%4,%5,%6,%7}, {%8,%9}, {%0,%1,%2,%3};"
        : "+f"(c[0]), "+f"(c[1]), "+f"(c[2]), "+f"(c[3])
        : "r"(a[0]), "r"(a[1]), "r"(a[2]), "r"(a[3]), "r"(b[0]), "r"(b[1]));
}
__device__ __forceinline__ float gelu_f(float x) {
    float x3 = x*x*x;
    return 0.5f * x * (1.0f + tanhf(0.79788456080286536f * (x + 0.044715f*x3)));
}

// ---------------- TF32 pre-round ----------------
__global__ __launch_bounds__(256)
void round_tf32_kernel(const float* __restrict__ src, float* __restrict__ dst, int n4) {
    int i = blockIdx.x*256 + threadIdx.x;
    if (i < n4) {
        float4 v = ((const float4*)src)[i];
        v.x = rtf32(v.x); v.y = rtf32(v.y); v.z = rtf32(v.z); v.w = rtf32(v.w);
        ((float4*)dst)[i] = v;
    }
}

// ---------------- LayerNorm (tf32-rounded output) ----------------
__global__ __launch_bounds__(256)
void ln_kernel(const float* __restrict__ x, const float* __restrict__ sc,
               const float* __restrict__ sh, float* __restrict__ out) {
    int row = blockIdx.x;
    const float* xr = x + (size_t)row * DD;
    float v[8];
    float s = 0.f, sq = 0.f;
#pragma unroll
    for (int i = 0; i < 8; i++) {
        v[i] = xr[threadIdx.x + i*256];
        s += v[i]; sq += v[i]*v[i];
    }
    __shared__ float rs[8], rq[8];
    __shared__ float s_mean, s_rstd;
#pragma unroll
    for (int o = 16; o > 0; o >>= 1) {
        s  += __shfl_down_sync(0xFFFFFFFFu, s,  o);
        sq += __shfl_down_sync(0xFFFFFFFFu, sq, o);
    }
    int w = threadIdx.x >> 5;
    if ((threadIdx.x & 31) == 0) { rs[w] = s; rq[w] = sq; }
    __syncthreads();
    if (threadIdx.x == 0) {
        float ts = 0.f, tq = 0.f;
#pragma unroll
        for (int i = 0; i < 8; i++) { ts += rs[i]; tq += rq[i]; }
        float mean = ts * (1.0f/DD);
        s_mean = mean;
        s_rstd = rsqrtf(tq * (1.0f/DD) - mean*mean + EPSV);
    }
    __syncthreads();
    float mean = s_mean, rstd = s_rstd;
    float* orow = out + (size_t)row * DD;
#pragma unroll
    for (int i = 0; i < 8; i++) {
        int d = threadIdx.x + i*256;
        orow[d] = rtf32(sc[d]*(v[i]-mean)*rstd + sh[d]);
    }
}

// ---------------- TF32 tensor-core GEMM ----------------
#define KSTEP   32
#define NSTG    3
#define A_ROWF  36
#define B_ROWF  136
#define A_BYTES (128*A_ROWF*4)
#define B_BYTES (KSTEP*B_ROWF*4)
#define STG_B   (A_BYTES + B_BYTES)
#define G_SMEM  (NSTG*STG_B)

template<int EPI>
__global__ __launch_bounds__(256, 2)
void mma_gemm(const float* __restrict__ A, const float* __restrict__ B,
              const float* __restrict__ bias, const float* __restrict__ R,
              float* __restrict__ C, int N, int K) {
    extern __shared__ char dsm[];
    const int tid = threadIdx.x;
    const int lane = tid & 31;
    const int wid = tid >> 5;
    const int warpM = wid & 1;
    const int warpN = wid >> 1;
    const int m0 = blockIdx.y * 128;
    const int n0 = blockIdx.x * 128;
    const uint32_t sb = smem_u32(dsm);

    float acc[4][4][4];
#pragma unroll
    for (int i = 0; i < 4; i++)
#pragma unroll
        for (int j = 0; j < 4; j++)
#pragma unroll
            for (int u = 0; u < 4; u++) acc[i][j][u] = 0.f;

    const int NT = K / KSTEP;

    auto load_stage = [&](int s, int kk) {
        uint32_t ab = sb + s*STG_B;
        uint32_t bbase = ab + A_BYTES;
#pragma unroll
        for (int i = 0; i < 4; i++) {
            int idx = i*256 + tid;
            int r = idx >> 3, c = idx & 7;
            cp_async16(ab + r*(A_ROWF*4) + c*16,
                       A + (size_t)(m0 + r)*K + kk + c*4);
        }
#pragma unroll
        for (int i = 0; i < 4; i++) {
            int idx = i*256 + tid;
            int r = idx >> 5, c = idx & 31;
            cp_async16(bbase + r*(B_ROWF*4) + c*16,
                       B + (size_t)(kk + r)*N + n0 + c*4);
        }
    };

    load_stage(0, 0); cp_commit();
    load_stage(1, KSTEP); cp_commit();

    const uint32_t* As_u = (const uint32_t*)dsm;
    const int arow = warpM*64 + (lane >> 2);
    const int acol = lane & 3;
    const int bcol = warpN*32 + (lane >> 2);
    const int brow = lane & 3;

    for (int t = 0; t < NT; t++) {
        cp_wait1();
        __syncthreads();
        if (t + 2 < NT) { load_stage((t+2)%NSTG, (t+2)*KSTEP); cp_commit(); }

        int s = t % NSTG;
        const uint32_t* Au = As_u + s*(STG_B/4);
        const uint32_t* Bu = Au + (A_BYTES/4);
#pragma unroll
        for (int k8 = 0; k8 < 4; k8++) {
            int kb = k8*8;
            uint32_t afr[4][4];
#pragma unroll
            for (int mt = 0; mt < 4; mt++) {
                int r = arow + mt*16;
                afr[mt][0] = Au[(r  )*A_ROWF + kb + acol    ];
                afr[mt][1] = Au[(r+8)*A_ROWF + kb + acol    ];
                afr[mt][2] = Au[(r  )*A_ROWF + kb + acol + 4];
                afr[mt][3] = Au[(r+8)*A_ROWF + kb + acol + 4];
            }
            uint32_t bfr[4][2];
#pragma unroll
            for (int nt = 0; nt < 4; nt++) {
                int cc = bcol + nt*8;
                bfr[nt][0] = Bu[(kb + brow    )*B_ROWF + cc];
                bfr[nt][1] = Bu[(kb + brow + 4)*B_ROWF + cc];
            }
#pragma unroll
            for (int mt = 0; mt < 4; mt++)
#pragma unroll
                for (int nt = 0; nt < 4; nt++)
                    mma_tf32(acc[mt][nt], afr[mt], bfr[nt]);
        }
        __syncthreads();
    }

#pragma unroll
    for (int mt = 0; mt < 4; mt++) {
#pragma unroll
        for (int half = 0; half < 2; half++) {
            int m = m0 + warpM*64 + mt*16 + (lane >> 2) + half*8;
#pragma unroll
            for (int nt = 0; nt < 4; nt++) {
                int n = n0 + warpN*32 + nt*8 + 2*(lane & 3);
                float v0 = acc[mt][nt][half*2 + 0];
                float v1 = acc[mt][nt][half*2 + 1];
                if (EPI == 1) {
                    const float2 bb = *(const float2*)(bias + n);
                    const float2 rr = *(const float2*)(R + (size_t)m*N + n);
                    v0 += bb.x + rr.x;
                    v1 += bb.y + rr.y;
                } else if (EPI == 2) {
                    const float2 bb = *(const float2*)(bias + n);
                    v0 = rtf32(gelu_f(v0 + bb.x));
                    v1 = rtf32(gelu_f(v1 + bb.y));
                }
                float2 o; o.x = v0; o.y = v1;
                *(float2*)(C + (size_t)m*N + n) = o;
            }
        }
    }
}

// ---------------- causal flash attention (TF32 tensor cores) ----------------
// 256 threads / 8 warps; Q tile 128 rows (16 per warp), K tile 64.
// Qs[128][132], Ks[64][132], Vt[128][68] (V transposed), Ps[128][68].
#define QROWF 132
#define VROWF 68
#define ATT_SMEM ((128*QROWF + 64*QROWF + 128*VROWF + 128*VROWF) * 4)

__global__ __launch_bounds__(256, 1)
void attn_mma(const float* __restrict__ Q, const float* __restrict__ Kg,
              const float* __restrict__ V, float* __restrict__ O) {
    extern __shared__ float sm[];
    float* Qs = sm;                    // [128][132]
    float* Ks = Qs + 128*QROWF;        // [64][132]
    float* Vt = Ks + 64*QROWF;         // [128][68]  Vt[d][key]
    float* Ps = Vt + 128*VROWF;        // [128][68]

    const int tid = threadIdx.x;
    const int lane = tid & 31;
    const int w = tid >> 5;
    const int r0 = lane >> 2;          // 0..7
    const int c0 = lane & 3;           // 0..3
    const int q0 = blockIdx.x * 128;
    const int b = blockIdx.y >> 4;
    const int h = blockIdx.y & 15;
    const float rscale = 0.08838834764831845f;
    size_t base = ((size_t)b * SS) * DD + (size_t)h * HD;

    // Q tile (pre-scaled, tf32-rounded)
#pragma unroll
    for (int i = 0; i < 16; i++) {
        int idx = i*256 + tid;
        int r = idx >> 5, c = (idx & 31)*4;
        float4 qv = *(const float4*)(Q + base + (size_t)(q0 + r)*DD + c);
        float* dst = Qs + r*QROWF + c;
        dst[0] = rtf32(qv.x*rscale); dst[1] = rtf32(qv.y*rscale);
        dst[2] = rtf32(qv.z*rscale); dst[3] = rtf32(qv.w*rscale);
    }

    float acc[16][4];
#pragma unroll
    for (int i = 0; i < 16; i++)
#pragma unroll
        for (int u = 0; u < 4; u++) acc[i][u] = 0.f;
    float m0r = -1e30f, m1r = -1e30f, l0r = 0.f, l1r = 0.f;
    const int qi0 = q0 + w*16 + r0;
    const int qi1 = qi0 + 8;

    const int nkt = (q0 >> 6) + 2;
    for (int kt = 0; kt < nkt; kt++) {
        int k0 = kt * 64;
        __syncthreads();
        // load K (row-major) and V (transposed), tf32-rounded
#pragma unroll
        for (int i = 0; i < 8; i++) {
            int idx = i*256 + tid;
            int r = idx >> 5, c = (idx & 31)*4;
            float4 kv = *(const float4*)(Kg + base + (size_t)(k0 + r)*DD + c);
            float* kd = Ks + r*QROWF + c;
            kd[0] = rtf32(kv.x); kd[1] = rtf32(kv.y);
            kd[2] = rtf32(kv.z); kd[3] = rtf32(kv.w);
            int vk = idx & 63, vd = (idx >> 6)*4;
            float4 vv = *(const float4*)(V + base + (size_t)(k0 + vk)*DD + vd);
            Vt[(vd+0)*VROWF + vk] = rtf32(vv.x);
            Vt[(vd+1)*VROWF + vk] = rtf32(vv.y);
            Vt[(vd+2)*VROWF + vk] = rtf32(vv.z);
            Vt[(vd+3)*VROWF + vk] = rtf32(vv.w);
        }
        __syncthreads();

        // S = Q @ K^T (warp rows x 64 keys)
        float s[8][4];
#pragma unroll
        for (int nt = 0; nt < 8; nt++)
#pragma unroll
            for (int u = 0; u < 4; u++) s[nt][u] = 0.f;
        const uint32_t* Qu = (const uint32_t*)Qs;
        const uint32_t* Ku = (const uint32_t*)Ks;
#pragma unroll
        for (int kc = 0; kc < 16; kc++) {
            int kb = kc*8;
            uint32_t a[4];
            int ra = (w*16 + r0)*QROWF + kb + c0;
            a[0] = Qu[ra];
            a[1] = Qu[ra + 8*QROWF];
            a[2] = Qu[ra + 4];
            a[3] = Qu[ra + 8*QROWF + 4];
#pragma unroll
            for (int nt = 0; nt < 8; nt++) {
                uint32_t bb[2];
                int rb = (nt*8 + r0)*QROWF + kb + c0;
                bb[0] = Ku[rb];
                bb[1] = Ku[rb + 4];
                mma_tf32(s[nt], a, bb);
            }
        }
        // causal mask (only diagonal-intersecting tiles)
        if (k0 + 63 > qi0) {
#pragma unroll
            for (int nt = 0; nt < 8; nt++) {
                int cj = k0 + nt*8 + 2*c0;
                if (cj     > qi0) s[nt][0] = -1e30f;
                if (cj + 1 > qi0) s[nt][1] = -1e30f;
                if (cj     > qi1) s[nt][2] = -1e30f;
                if (cj + 1 > qi1) s[nt][3] = -1e30f;
            }
        }
        // online softmax (rows qi0, qi1)
        float tm0 = -1e30f, tm1 = -1e30f;
#pragma unroll
        for (int nt = 0; nt < 8; nt++) {
            tm0 = fmaxf(tm0, fmaxf(s[nt][0], s[nt][1]));
            tm1 = fmaxf(tm1, fmaxf(s[nt][2], s[nt][3]));
        }
        tm0 = fmaxf(tm0, __shfl_xor_sync(0xFFFFFFFFu, tm0, 1));
        tm0 = fmaxf(tm0, __shfl_xor_sync(0xFFFFFFFFu, tm0, 2));
        tm1 = fmaxf(tm1, __shfl_xor_sync(0xFFFFFFFFu, tm1, 1));
        tm1 = fmaxf(tm1, __shfl_xor_sync(0xFFFFFFFFu, tm1, 2));
        float mn0 = fmaxf(m0r, tm0), f0 = __expf(m0r - mn0);
        float mn1 = fmaxf(m1r, tm1), f1 = __expf(m1r - mn1);
        float ps0 = 0.f, ps1 = 0.f;
#pragma unroll
        for (int nt = 0; nt < 8; nt++) {
            float p0 = __expf(s[nt][0] - mn0);
            float p1 = __expf(s[nt][1] - mn0);
            float p2 = __expf(s[nt][2] - mn1);
            float p3 = __expf(s[nt][3] - mn1);
            ps0 += p0 + p1; ps1 += p2 + p3;
            s[nt][0] = rtf32(p0); s[nt][1] = rtf32(p1);
            s[nt][2] = rtf32(p2); s[nt][3] = rtf32(p3);
        }
        ps0 += __shfl_xor_sync(0xFFFFFFFFu, ps0, 1);
        ps0 += __shfl_xor_sync(0xFFFFFFFFu, ps0, 2);
        ps1 += __shfl_xor_sync(0xFFFFFFFFu, ps1, 1);
        ps1 += __shfl_xor_sync(0xFFFFFFFFu, ps1, 2);
        l0r = l0r*f0 + ps0; m0r = mn0;
        l1r = l1r*f1 + ps1; m1r = mn1;
        // write P (warp-private rows)
#pragma unroll
        for (int nt = 0; nt < 8; nt++) {
            int col = nt*8 + 2*c0;
            float2 p01; p01.x = s[nt][0]; p01.y = s[nt][1];
            float2 p23; p23.x = s[nt][2]; p23.y = s[nt][3];
            *(float2*)(Ps + (w*16 + r0    )*VROWF + col) = p01;
            *(float2*)(Ps + (w*16 + r0 + 8)*VROWF + col) = p23;
        }
        __syncwarp();
        // rescale accumulators
#pragma unroll
        for (int nt = 0; nt < 16; nt++) {
            acc[nt][0] *= f0; acc[nt][1] *= f0;
            acc[nt][2] *= f1; acc[nt][3] *= f1;
        }
        // O += P @ V  (A = Ps warp rows, B = Vt[d][key])
        const uint32_t* Pu = (const uint32_t*)Ps;
        const uint32_t* Vu = (const uint32_t*)Vt;
#pragma unroll
        for (int kc = 0; kc < 8; kc++) {
            int kb = kc*8;
            uint32_t a[4];
            int ra = (w*16 + r0)*VROWF + kb + c0;
            a[0] = Pu[ra];
            a[1] = Pu[ra + 8*VROWF];
            a[2] = Pu[ra + 4];
            a[3] = Pu[ra + 8*VROWF + 4];
#pragma unroll
            for (int nt = 0; nt < 16; nt++) {
                uint32_t bb[2];
                int rb = (nt*8 + r0)*VROWF + kb + c0;
                bb[0] = Vu[rb];
                bb[1] = Vu[rb + 4];
                mma_tf32(acc[nt], a, bb);
            }
        }
    }

    // epilogue: ctx = acc / l, tf32-rounded (feeds Wo GEMM)
    float inv0 = 1.0f / l0r, inv1 = 1.0f / l1r;
#pragma unroll
    for (int nt = 0; nt < 16; nt++) {
        int n = nt*8 + 2*c0;
        float2 o0, o1;
        o0.x = rtf32(acc[nt][0]*inv0); o0.y = rtf32(acc[nt][1]*inv0);
        o1.x = rtf32(acc[nt][2]*inv1); o1.y = rtf32(acc[nt][3]*inv1);
        *(float2*)(O + base + (size_t)qi0*DD + n) = o0;
        *(float2*)(O + base + (size_t)qi1*DD + n) = o1;
    }
}

// ---------------- launch ----------------
extern "C" void kernel_launch(void* const* d_in, const int* in_sizes, int n_in,
                              void* d_out, int out_size) {
    const float* x    = (const float*)d_in[0];
    const float* Wq   = (const float*)d_in[1];
    const float* Wk   = (const float*)d_in[2];
    const float* Wv   = (const float*)d_in[3];
    const float* Wo   = (const float*)d_in[4];
    const float* bo   = (const float*)d_in[5];
    const float* ln1s = (const float*)d_in[6];
    const float* ln1b = (const float*)d_in[7];
    const float* ln2s = (const float*)d_in[8];
    const float* ln2b = (const float*)d_in[9];
    const float* W1   = (const float*)d_in[10];
    const float* b1   = (const float*)d_in[11];
    const float* W2   = (const float*)d_in[12];
    const float* b2   = (const float*)d_in[13];
    float* out = (float*)d_out;

    float *xn, *q, *k, *v, *ctx, *h, *ff;
    float *wq, *wk, *wv, *wo, *w1, *w2;
    cudaGetSymbolAddress((void**)&xn,  g_xn);
    cudaGetSymbolAddress((void**)&q,   g_q);
    cudaGetSymbolAddress((void**)&k,   g_k);
    cudaGetSymbolAddress((void**)&v,   g_v);
    cudaGetSymbolAddress((void**)&ctx, g_ctx);
    cudaGetSymbolAddress((void**)&h,   g_h);
    cudaGetSymbolAddress((void**)&ff,  g_ff);
    cudaGetSymbolAddress((void**)&wq,  g_wq);
    cudaGetSymbolAddress((void**)&wk,  g_wk);
    cudaGetSymbolAddress((void**)&wv,  g_wv);
    cudaGetSymbolAddress((void**)&wo,  g_wo);
    cudaGetSymbolAddress((void**)&w1,  g_w1);
    cudaGetSymbolAddress((void**)&w2,  g_w2);

    cudaFuncSetAttribute(attn_mma, cudaFuncAttributeMaxDynamicSharedMemorySize, ATT_SMEM);
    cudaFuncSetAttribute(mma_gemm<0>, cudaFuncAttributeMaxDynamicSharedMemorySize, G_SMEM);
    cudaFuncSetAttribute(mma_gemm<1>, cudaFuncAttributeMaxDynamicSharedMemorySize, G_SMEM);
    cudaFuncSetAttribute(mma_gemm<2>, cudaFuncAttributeMaxDynamicSharedMemorySize, G_SMEM);

    const int n4a = DD*DD/4, n4b = DD*DFF/4;
    round_tf32_kernel<<<(n4a+255)/256, 256>>>(Wq, wq, n4a);
    round_tf32_kernel<<<(n4a+255)/256, 256>>>(Wk, wk, n4a);
    round_tf32_kernel<<<(n4a+255)/256, 256>>>(Wv, wv, n4a);
    round_tf32_kernel<<<(n4a+255)/256, 256>>>(Wo, wo, n4a);
    round_tf32_kernel<<<(n4b+255)/256, 256>>>(W1, w1, n4b);
    round_tf32_kernel<<<(n4b+255)/256, 256>>>(W2, w2, n4b);

    ln_kernel<<<MROW, 256>>>(x, ln1s, ln1b, xn);
    mma_gemm<0><<<dim3(DD/128, MROW/128), 256, G_SMEM>>>(xn, wq, nullptr, nullptr, q, DD, DD);
    mma_gemm<0><<<dim3(DD/128, MROW/128), 256, G_SMEM>>>(xn, wk, nullptr, nullptr, k, DD, DD);
    mma_gemm<0><<<dim3(DD/128, MROW/128), 256, G_SMEM>>>(xn, wv, nullptr, nullptr, v, DD, DD);
    attn_mma<<<dim3(SS/128, BB*HH), 256, ATT_SMEM>>>(q, k, v, ctx);
    mma_gemm<1><<<dim3(DD/128, MROW/128), 256, G_SMEM>>>(ctx, wo, bo, x, h, DD, DD);
    ln_kernel<<<MROW, 256>>>(h, ln2s, ln2b, xn);
    mma_gemm<2><<<dim3(DFF/128, MROW/128), 256, G_SMEM>>>(xn, w1, b1, nullptr, ff, DFF, DD);
    mma_gemm<1><<<dim3(DD/128, MROW/128), 256, G_SMEM>>>(ff, w2, b2, h, out, DD, DFF);
}